// round 6
// baseline (speedup 1.0000x reference)
#include <cuda_runtime.h>
#include <cuda_bf16.h>
#include <math.h>

// Problem constants
#define BZ   128
#define T_   32
#define D_   768
#define DFF_ 3072
#define E_   8
#define BEAMS_ 2
#define NROWS (BZ * BEAMS_)                    // 256
#define OUT_ELEMS ((size_t)NROWS * T_ * D_)    // 6,291,456

// Scratch: h = gelu(x @ W1 + b1), 256 x 32 x 3072 fp32 = ~100 MB
__device__ __align__(256) float g_h[(size_t)NROWS * T_ * DFF_];
// Routing state
__device__ int g_sel[NROWS];
__device__ int g_cnt[E_];
__device__ int g_rows[E_][NROWS];

// ---------------------------------------------------------------------------
// Gating: mean-pool over T, logits = avg @ Wg, softmax, top-2 (stable ties)
// ---------------------------------------------------------------------------
__global__ void gate_kernel(const float* __restrict__ x,
                            const float* __restrict__ Wg,
                            float* __restrict__ out, int out_size)
{
    const int b = blockIdx.x;
    const int t = threadIdx.x;
    __shared__ float s_avg[D_];
    __shared__ float s_logits[E_];

    const float* xb = x + (size_t)b * T_ * D_;
    for (int d = t; d < D_; d += 256) {
        float s = 0.f;
        #pragma unroll
        for (int tt = 0; tt < T_; tt++) s += xb[tt * D_ + d];
        s_avg[d] = s * (1.0f / (float)T_);
    }
    __syncthreads();

    const int w = t >> 5, lane = t & 31;
    float p = 0.f;
    for (int d = lane; d < D_; d += 32) p += s_avg[d] * Wg[d * E_ + w];
    #pragma unroll
    for (int o = 16; o; o >>= 1) p += __shfl_xor_sync(0xffffffffu, p, o);
    if (lane == 0) s_logits[w] = p;
    __syncthreads();

    if (t == 0) {
        float mx = s_logits[0];
        #pragma unroll
        for (int e = 1; e < E_; e++) mx = fmaxf(mx, s_logits[e]);
        float pr[E_]; float se = 0.f;
        #pragma unroll
        for (int e = 0; e < E_; e++) { pr[e] = expf(s_logits[e] - mx); se += pr[e]; }
        float inv = 1.0f / se;
        #pragma unroll
        for (int e = 0; e < E_; e++) pr[e] *= inv;

        int i1 = 0;
        #pragma unroll
        for (int e = 1; e < E_; e++) if (pr[e] > pr[i1]) i1 = e;
        int i2 = -1;
        #pragma unroll
        for (int e = 0; e < E_; e++) {
            if (e == i1) continue;
            if (i2 < 0 || pr[e] > pr[i2]) i2 = e;
        }

        g_sel[2 * b + 0] = i1;
        g_sel[2 * b + 1] = i2;

        if (out_size >= (int)(OUT_ELEMS + 2 * NROWS)) {
            out[OUT_ELEMS + 2 * b + 0] = pr[i1];
            out[OUT_ELEMS + 2 * b + 1] = pr[i2];
            out[OUT_ELEMS + NROWS + 2 * b + 0] = (float)i1;
            out[OUT_ELEMS + NROWS + 2 * b + 1] = (float)i2;
        }
    }
}

__global__ void route_build_kernel()
{
    if (threadIdx.x == 0 && blockIdx.x == 0) {
        int cnt[E_];
        #pragma unroll
        for (int e = 0; e < E_; e++) cnt[e] = 0;
        for (int n = 0; n < NROWS; n++) {
            int e = g_sel[n];
            g_rows[e][cnt[e]++] = n;
        }
        #pragma unroll
        for (int e = 0; e < E_; e++) g_cnt[e] = cnt[e];
    }
}

// ---------------------------------------------------------------------------
// TF32 grouped GEMM: 128x128 block tile, 8 warps (4m x 2n), warp tile 32x64.
// - cvt.rna at STS (once per element), smem holds tf32 bits
// - A smem [m][k] (32 floats/row), B smem [n][k] (transposed at STS)
// - XOR swizzle: granule ^= (row & 7)  -> STS and LDSM both conflict-free
// - ldmatrix.x4 fragment loads
// - 3-stage smem ring, 1 barrier per iter
// ---------------------------------------------------------------------------
#define STAGE_BYTES   16384                     // 128 rows * 32 floats * 4B
#define NSTAGES       3
#define A_BASE        0
#define B_BASE        (NSTAGES * STAGE_BYTES)   // 49152
#define SMEM_BYTES    (2 * NSTAGES * STAGE_BYTES)  // 98304

__device__ __forceinline__ unsigned f2tf(float f) {
    unsigned u;
    asm("cvt.rna.tf32.f32 %0, %1;" : "=r"(u) : "f"(f));
    return u;
}

__device__ __forceinline__ void mma_tf32(float* c, const unsigned* a, const unsigned* b) {
    asm volatile(
        "mma.sync.aligned.m16n8k8.row.col.f32.tf32.tf32.f32 "
        "{%0,%1,%2,%3}, {%4,%5,%6,%7}, {%8,%9}, {%0,%1,%2,%3};"
        : "+f"(c[0]), "+f"(c[1]), "+f"(c[2]), "+f"(c[3])
        : "r"(a[0]), "r"(a[1]), "r"(a[2]), "r"(a[3]), "r"(b[0]), "r"(b[1]));
}

__device__ __forceinline__ void ldsm_x4(unsigned& r0, unsigned& r1,
                                        unsigned& r2, unsigned& r3, unsigned addr) {
    asm volatile("ldmatrix.sync.aligned.m8n8.x4.shared.b16 {%0,%1,%2,%3}, [%4];"
                 : "=r"(r0), "=r"(r1), "=r"(r2), "=r"(r3) : "r"(addr));
}

__device__ __forceinline__ float gelu_exact(float v) {
    return 0.5f * v * (1.0f + erff(v * 0.70710678118654752f));
}

template <int KDIM, int NDIM, bool GELU, bool HALF_IN, bool OUT_GH, bool IN_GH>
__global__ __launch_bounds__(256, 2)
void moe_gemm(const float* __restrict__ Aarg,
              const float* __restrict__ Wbase,
              const float* __restrict__ Bbase,
              float* __restrict__ Oarg)
{
    const int e     = blockIdx.z;
    const int cnt   = g_cnt[e];
    const int mtile = blockIdx.y;
    if (mtile * 4 >= cnt) return;
    const int ntile = blockIdx.x;

    extern __shared__ char smem_raw[];
    char* smem = smem_raw;
    const unsigned smem_u32 = (unsigned)__cvta_generic_to_shared(smem);
    __shared__ int s_rows[4];

    const int t = threadIdx.x;      // 0..255
    if (t < 4) {
        int idx = mtile * 4 + t;
        s_rows[t] = (idx < cnt) ? g_rows[e][idx] : -1;
    }
    __syncthreads();

    const float* A0   = IN_GH ? g_h : Aarg;
    const float* W    = Wbase + (size_t)e * KDIM * NDIM + (size_t)ntile * 128;
    const float* bias = Bbase + (size_t)e * NDIM + ntile * 128;

    const int warp = t >> 5, lane = t & 31;
    const int wm = (warp & 3) * 32;         // 4 warps along m
    const int wn = (warp >> 2) * 64;        // 2 warps along n

    float acc[2][8][4];
    #pragma unroll
    for (int i = 0; i < 2; i++)
        #pragma unroll
        for (int j = 0; j < 8; j++)
            #pragma unroll
            for (int q = 0; q < 4; q++) acc[i][j][q] = 0.f;

    // ---- per-thread load-phase addressing -------------------------------
    // A tile 128m x 32k: 4 groups of (m, k-quad). LDG.128 along k.
    const float* a_ptr[4];
    int a_sts[4];                            // byte offset within A stage
    #pragma unroll
    for (int g = 0; g < 4; g++) {
        int idx = t + g * 256;               // 0..1023
        int m   = idx >> 3;                  // 0..127
        int kq  = idx & 7;                   // 0..7
        int r   = s_rows[m >> 5];
        if (r < 0) r = s_rows[0];
        int arow = HALF_IN ? (r >> 1) : r;
        a_ptr[g] = A0 + ((size_t)arow * T_ + (m & 31)) * (size_t)KDIM + kq * 4;
        a_sts[g] = m * 128 + ((kq ^ (m & 7)) << 4);
    }
    // B tile 32k x 128n (gmem [k][n]) -> smem [n][k]: 4 groups of (n, k-quad),
    // 4 strided LDG.32 (coalesced across warp), one STS.128 per group.
    const float* b_ptr[4];
    int b_sts[4];
    #pragma unroll
    for (int g = 0; g < 4; g++) {
        int idx = t + g * 256;
        int n   = idx & 127;
        int kq  = idx >> 7;                  // 0..7
        b_ptr[g] = W + (size_t)(kq * 4) * NDIM + n;
        b_sts[g] = n * 128 + ((kq ^ (n & 7)) << 4);
    }

    // ---- fragment (ldmatrix) addressing ---------------------------------
    const int rin = lane & 7;                // row-within-matrix; == row&7
    // A: mat = lane>>3: row-half bit = mat&1, granule bit = mat>>1
    const int amrow0 = wm + (((lane >> 3) & 1) << 3) + rin;      // i = 0
    const int a_row_b0 = amrow0 * 128;                           // bytes
    const int a_gbit   = lane >> 4;
    // B: mat: n-half bit = mat>>1, granule bit = mat&1
    const int bnrow0 = wn + ((lane >> 4) << 3) + rin;            // jj = 0
    const int b_gbit = (lane >> 3) & 1;

    const int iters = KDIM / 32;

    // ---- load stage s (k0 = s*32) into ring slot -------------------------
    auto load_stage = [&](int s, int slot) {
        const int k0 = s * 32;
        float4 av[4];
        #pragma unroll
        for (int g = 0; g < 4; g++)
            av[g] = *(const float4*)(a_ptr[g] + k0);
        float bv[4][4];
        #pragma unroll
        for (int g = 0; g < 4; g++)
            #pragma unroll
            for (int kk = 0; kk < 4; kk++)
                bv[g][kk] = b_ptr[g][(size_t)(k0 + kk) * NDIM];

        char* Ad = smem + A_BASE + slot * STAGE_BYTES;
        char* Bd = smem + B_BASE + slot * STAGE_BYTES;
        #pragma unroll
        for (int g = 0; g < 4; g++) {
            uint4 u = make_uint4(f2tf(av[g].x), f2tf(av[g].y),
                                 f2tf(av[g].z), f2tf(av[g].w));
            *(uint4*)(Ad + a_sts[g]) = u;
        }
        #pragma unroll
        for (int g = 0; g < 4; g++) {
            uint4 u = make_uint4(f2tf(bv[g][0]), f2tf(bv[g][1]),
                                 f2tf(bv[g][2]), f2tf(bv[g][3]));
            *(uint4*)(Bd + b_sts[g]) = u;
        }
    };

    // Prologue
    load_stage(0, 0);

    int slot = 0, nslot = 1;
    for (int it = 0; it < iters; it++) {
        if (it + 1 < iters) load_stage(it + 1, nslot);
        __syncthreads();

        const unsigned Au = smem_u32 + A_BASE + slot * STAGE_BYTES;
        const unsigned Bu = smem_u32 + B_BASE + slot * STAGE_BYTES;

        #pragma unroll
        for (int ks = 0; ks < 4; ks++) {
            unsigned a[2][4], b[8][2];
            // A fragments: 2 ldmatrix.x4
            {
                int gA = 2 * ks + a_gbit;
                unsigned off0 = Au + a_row_b0 + ((gA ^ rin) << 4);
                ldsm_x4(a[0][0], a[0][1], a[0][2], a[0][3], off0);
                ldsm_x4(a[1][0], a[1][1], a[1][2], a[1][3], off0 + 16 * 128);
            }
            // B fragments: 4 ldmatrix.x4 (each covers j, j+1)
            {
                int gB = 2 * ks + b_gbit;
                unsigned base = Bu + bnrow0 * 128 + ((gB ^ rin) << 4);
                #pragma unroll
                for (int jj = 0; jj < 4; jj++) {
                    ldsm_x4(b[2 * jj][0], b[2 * jj][1],
                            b[2 * jj + 1][0], b[2 * jj + 1][1],
                            base + jj * (16 * 128));
                }
            }
            #pragma unroll
            for (int i = 0; i < 2; i++)
                #pragma unroll
                for (int j = 0; j < 8; j++)
                    mma_tf32(acc[i][j], a[i], b[j]);
        }
        // rotate ring
        slot = nslot;
        nslot = nslot + 1 == NSTAGES ? 0 : nslot + 1;
    }

    // --- epilogue: bias (+GELU), scatter to gathered output rows ---
    #pragma unroll
    for (int i = 0; i < 2; i++) {
        int r0 = wm + i * 16 + (lane >> 2);
        #pragma unroll
        for (int half = 0; half < 2; half++) {
            int gm   = r0 + half * 8;
            int grow = s_rows[gm >> 5];
            if (grow < 0) continue;
            float* orow = (OUT_GH ? g_h : Oarg)
                        + ((size_t)grow * T_ + (gm & 31)) * (size_t)NDIM
                        + (size_t)ntile * 128;
            #pragma unroll
            for (int j = 0; j < 8; j++) {
                int c0 = wn + j * 8 + 2 * (lane & 3);
                float v0 = acc[i][j][half * 2 + 0] + bias[c0];
                float v1 = acc[i][j][half * 2 + 1] + bias[c0 + 1];
                if (GELU) { v0 = gelu_exact(v0); v1 = gelu_exact(v1); }
                orow[c0]     = v0;
                orow[c0 + 1] = v1;
            }
        }
    }
}

// ---------------------------------------------------------------------------
// Launch
// ---------------------------------------------------------------------------
extern "C" void kernel_launch(void* const* d_in, const int* in_sizes, int n_in,
                              void* d_out, int out_size)
{
    const float* x  = (const float*)d_in[0];
    const float* Wg = (const float*)d_in[2];
    const float* W1 = (const float*)d_in[3];
    const float* b1 = (const float*)d_in[4];
    const float* W2 = (const float*)d_in[5];
    const float* b2 = (const float*)d_in[6];
    float* out = (float*)d_out;

    cudaFuncSetAttribute(moe_gemm<D_, DFF_, true, true, true, false>,
                         cudaFuncAttributeMaxDynamicSharedMemorySize, SMEM_BYTES);
    cudaFuncSetAttribute(moe_gemm<DFF_, D_, false, false, false, true>,
                         cudaFuncAttributeMaxDynamicSharedMemorySize, SMEM_BYTES);

    // 1) Gating + routing
    gate_kernel<<<BZ, 256>>>(x, Wg, out, out_size);
    route_build_kernel<<<1, 32>>>();

    // 2) h = gelu(x[n/2] @ W1[sel] + b1[sel])  (grouped by expert)
    moe_gemm<D_, DFF_, true, true, true, false>
        <<<dim3(DFF_ / 128, 64, E_), 256, SMEM_BYTES>>>(x, W1, b1, out);

    // 3) out = h @ W2[sel] + b2[sel]
    moe_gemm<DFF_, D_, false, false, false, true>
        <<<dim3(D_ / 128, 64, E_), 256, SMEM_BYTES>>>(x, W2, b2, out);
}